// round 8
// baseline (speedup 1.0000x reference)
#include <cuda_runtime.h>
#include <math.h>

// Shapes (fixed by the problem)
#define NB 4
#define NH 16
#define NS 1024
#define ND 1024
#define HD 64
#define NK2 512   // 2 * BUCKETS
#define SPAN 256  // BUCKETS

// ---------------- scratch (device globals; no allocs allowed) ----------------
__device__ float g_re[NK2 * ND];
__device__ float g_q[(size_t)NB * NH * NS * HD];
__device__ float g_k[(size_t)NB * NH * NS * HD];
__device__ float g_v[(size_t)NB * NH * NS * HD];
__device__ float g_posk[NH * NK2 * HD];
__device__ float g_posq[NH * NK2 * HD];
__device__ float g_c2p[(size_t)NB * NH * NS * NK2];
__device__ float g_p2c[(size_t)NB * NH * NS * NK2];
__device__ float g_ctx[(size_t)NB * NS * ND];
__device__ int   g_tbl[2 * NS - 1];

// ---------------- helpers ----------------
__device__ __forceinline__ float f2tf(float x) {
    unsigned u;
    asm("cvt.rna.tf32.f32 %0, %1;" : "=r"(u) : "f"(x));
    return __uint_as_float(u);
}

__device__ __forceinline__ void mma_tf32(float* c, const float* a, const float* b) {
    asm volatile("mma.sync.aligned.m16n8k8.row.col.f32.tf32.tf32.f32 "
                 "{%0,%1,%2,%3}, {%4,%5,%6,%7}, {%8,%9}, {%0,%1,%2,%3};\n"
                 : "+f"(c[0]), "+f"(c[1]), "+f"(c[2]), "+f"(c[3])
                 : "r"(__float_as_uint(a[0])), "r"(__float_as_uint(a[1])),
                   "r"(__float_as_uint(a[2])), "r"(__float_as_uint(a[3])),
                   "r"(__float_as_uint(b[0])), "r"(__float_as_uint(b[1])));
}

__device__ __forceinline__ void cp16(float* dst, const float* src) {
    unsigned s = (unsigned)__cvta_generic_to_shared(dst);
    asm volatile("cp.async.cg.shared.global [%0], [%1], 16;" :: "r"(s), "l"(src));
}
__device__ __forceinline__ void cp_commit() { asm volatile("cp.async.commit_group;"); }
__device__ __forceinline__ void cp_wait0()  { asm volatile("cp.async.wait_group 0;"); }
__device__ __forceinline__ void cp_wait1()  { asm volatile("cp.async.wait_group 1;"); }
__device__ __forceinline__ void cp_wait2()  { asm volatile("cp.async.wait_group 2;"); }

// ---------------- bucket table ----------------
__global__ void build_tbl_kernel(int* tbl) {
    int i = blockIdx.x * blockDim.x + threadIdx.x;
    if (i >= 2 * NS - 1) return;
    int rel = i - (NS - 1);
    const float mid = 128.0f;
    float signf = (rel > 0) ? 1.0f : (rel < 0 ? -1.0f : 0.0f);
    float abs_pos = (rel < 128 && rel > -128) ? 127.0f : fabsf((float)rel);
    float bucket;
    if (abs_pos <= mid) {
        bucket = (float)rel;
    } else {
        const float LOGC = 1.3843393289f;  // log(511/128) as f32
        float log_pos = ceilf(logf(abs_pos / mid) / LOGC * 127.0f) + mid;
        bucket = log_pos * signf;
    }
    tbl[i] = (int)bucket;
}

// ---------------- LayerNorm for rel_emb [512,1024] ----------------
__global__ void ln_kernel(const float* __restrict__ x, const float* __restrict__ g,
                          const float* __restrict__ b, float* __restrict__ y) {
    int row = blockIdx.x;
    const float* xr = x + (size_t)row * ND;
    __shared__ float red[256];
    int tid = threadIdx.x;

    float s = 0.f;
    for (int i = tid; i < ND; i += 256) s += xr[i];
    red[tid] = s; __syncthreads();
    for (int o = 128; o > 0; o >>= 1) { if (tid < o) red[tid] += red[tid + o]; __syncthreads(); }
    float mu = red[0] * (1.0f / ND);
    __syncthreads();

    float v = 0.f;
    for (int i = tid; i < ND; i += 256) { float d = xr[i] - mu; v += d * d; }
    red[tid] = v; __syncthreads();
    for (int o = 128; o > 0; o >>= 1) { if (tid < o) red[tid] += red[tid + o]; __syncthreads(); }
    float var = red[0] * (1.0f / ND);
    float inv = 1.0f / sqrtf(var + 1e-5f);

    for (int i = tid; i < ND; i += 256)
        y[(size_t)row * ND + i] = (xr[i] - mu) * inv * g[i] + b[i];
}

// ============================================================================
// mm_jobs_tf32: up to 5 independent GEMMs C = A[M,1024] @ W[1024,1024] + bias.
// 128x128 tile, K-chunk 16, 4-stage cp.async pipeline, 1 sync/chunk,
// dynamic smem 75776 B, 2 CTAs/SM.
// ============================================================================
struct MMJob {
    const float* A; const float* W; const float* bias; float* C;
    int M; int splitR;   // splitR==0: row-major out; else head-split (+tf32 round)
};
struct MMJobs { MMJob j[5]; };

#define MM_AS 2560   // 128*20 floats per stage
#define MM_BS 2176   // 16*136 floats per stage

__global__ __launch_bounds__(256, 2) void mm_jobs_tf32(MMJobs jobs)
{
    extern __shared__ float sm[];
    float* As = sm;                 // [4][128][20]
    float* Bs = sm + 4 * MM_AS;     // [4][16][136]

    const MMJob jb = jobs.j[blockIdx.z];
    if (blockIdx.y * 128 >= jb.M) return;
    const float* A = jb.A; const float* W = jb.W;
    const float* bias = jb.bias; float* C = jb.C;
    const int splitR = jb.splitR;

    const int t = threadIdx.x, l = t & 31, w = t >> 5;
    const int gm = l >> 2, kq = l & 3;
    const int warpM = (w >> 1) * 32, warpN = (w & 1) * 64;
    const int rowBase = blockIdx.y * 128, colBase = blockIdx.x * 128;

    float acc[2][8][4];
#pragma unroll
    for (int i = 0; i < 2; ++i)
#pragma unroll
        for (int j = 0; j < 8; ++j)
#pragma unroll
            for (int e = 0; e < 4; ++e) acc[i][j][e] = 0.f;

    const int ar = t >> 1, ac = (t & 1) * 8;
    const int bk = t >> 4, bc = (t & 15) * 8;

    // prologue: chunks 0..2 into stages 0..2
#pragma unroll
    for (int p = 0; p < 3; ++p) {
        int k0 = p * 16;
        cp16(&As[p * MM_AS + ar * 20 + ac],     A + (size_t)(rowBase + ar) * ND + k0 + ac);
        cp16(&As[p * MM_AS + ar * 20 + ac + 4], A + (size_t)(rowBase + ar) * ND + k0 + ac + 4);
        cp16(&Bs[p * MM_BS + bk * 136 + bc],     W + (size_t)(k0 + bk) * ND + colBase + bc);
        cp16(&Bs[p * MM_BS + bk * 136 + bc + 4], W + (size_t)(k0 + bk) * ND + colBase + bc + 4);
        cp_commit();
    }

    for (int c = 0; c < 64; ++c) {
        cp_wait2();          // chunk c resident
        __syncthreads();     // all warps done with stage (c-1)&3 reads

        if (c + 3 < 64) {    // issue chunk c+3 into stage (c+3)&3 (== (c-1)&3)
            int k0 = (c + 3) * 16, s = (c + 3) & 3;
            cp16(&As[s * MM_AS + ar * 20 + ac],     A + (size_t)(rowBase + ar) * ND + k0 + ac);
            cp16(&As[s * MM_AS + ar * 20 + ac + 4], A + (size_t)(rowBase + ar) * ND + k0 + ac + 4);
            cp16(&Bs[s * MM_BS + bk * 136 + bc],     W + (size_t)(k0 + bk) * ND + colBase + bc);
            cp16(&Bs[s * MM_BS + bk * 136 + bc + 4], W + (size_t)(k0 + bk) * ND + colBase + bc + 4);
        }
        cp_commit();         // unconditional (keeps wait_group counting exact)

        const float* Ast = &As[(c & 3) * MM_AS];
        const float* Bst = &Bs[(c & 3) * MM_BS];
#pragma unroll
        for (int ks = 0; ks < 2; ++ks) {
            const int k = ks * 8;
            float a[2][4], b[8][2];
#pragma unroll
            for (int mt = 0; mt < 2; ++mt) {
                int m = warpM + mt * 16 + gm;
                a[mt][0] = f2tf(Ast[m * 20 + k + kq]);
                a[mt][1] = f2tf(Ast[(m + 8) * 20 + k + kq]);
                a[mt][2] = f2tf(Ast[m * 20 + k + kq + 4]);
                a[mt][3] = f2tf(Ast[(m + 8) * 20 + k + kq + 4]);
            }
#pragma unroll
            for (int nt = 0; nt < 8; ++nt) {
                int n = warpN + nt * 8 + gm;
                b[nt][0] = f2tf(Bst[(k + kq) * 136 + n]);
                b[nt][1] = f2tf(Bst[(k + kq + 4) * 136 + n]);
            }
#pragma unroll
            for (int mt = 0; mt < 2; ++mt)
#pragma unroll
                for (int nt = 0; nt < 8; ++nt)
                    mma_tf32(acc[mt][nt], a[mt], b[nt]);
        }
    }

#pragma unroll
    for (int mt = 0; mt < 2; ++mt) {
#pragma unroll
        for (int nt = 0; nt < 8; ++nt) {
            int r0 = rowBase + warpM + mt * 16 + gm;
            int c0 = colBase + warpN + nt * 8 + kq * 2;
#pragma unroll
            for (int half = 0; half < 2; ++half) {
                int r = r0 + half * 8;
                float v0 = acc[mt][nt][half * 2 + 0] + bias[c0];
                float v1 = acc[mt][nt][half * 2 + 1] + bias[c0 + 1];
                if (splitR == 0) {
                    *(float2*)&C[(size_t)r * ND + c0] = make_float2(v0, v1);
                } else {
                    v0 = f2tf(v0); v1 = f2tf(v1);
                    int h = c0 >> 6, d = c0 & 63;
                    int bb = r / splitR, rr = r - bb * splitR;
                    *(float2*)&C[(((size_t)bb * NH + h) * splitR + rr) * HD + d] =
                        make_float2(v0, v1);
                }
            }
        }
    }
}

// ============================================================================
// nt64_pair_tf32: c2p and p2c in one launch; whole-tile one-shot staging.
// z<64:  C2P[z][i][kk] = q[z] . posk[z%16]
// z>=64: P2C[z-64][i][kk] = k[z-64] . posq[(z-64)%16]
// Dynamic smem: 2*128*72*4 = 73728 B, 2 CTAs/SM.
// ============================================================================
__global__ __launch_bounds__(256, 2) void nt64_pair_tf32(
    const float* __restrict__ q, const float* __restrict__ posk,
    const float* __restrict__ kk, const float* __restrict__ posq,
    float* __restrict__ c2p, float* __restrict__ p2c)
{
    extern __shared__ float sm[];
    float (*Asm)[72] = (float(*)[72])sm;              // [128][72]
    float (*Bsm)[72] = (float(*)[72])(sm + 128 * 72); // [128][72]

    const int t = threadIdx.x, l = t & 31, w = t >> 5;
    const int gm = l >> 2, kq = l & 3;
    const int warpM = (w >> 1) * 32, warpN = (w & 1) * 64;
    const int zz = blockIdx.z;
    const int batch = zz & 63;
    const int iBase = blockIdx.y * 128, jBase = blockIdx.x * 128;

    const float* Ab = ((zz < 64) ? q : kk) + (size_t)batch * NS * HD;
    const float* Bb = ((zz < 64) ? posk : posq) + (size_t)(batch & 15) * NK2 * HD;
    float* Cb = ((zz < 64) ? c2p : p2c) + (size_t)batch * NS * NK2;

    const int sr = t >> 1, cb = (t & 1) * 32;

    // one-shot load of both 128x64 tiles
#pragma unroll
    for (int i = 0; i < 8; ++i)
        cp16(&Asm[sr][cb + i * 4], Ab + (size_t)(iBase + sr) * HD + cb + i * 4);
#pragma unroll
    for (int i = 0; i < 8; ++i)
        cp16(&Bsm[sr][cb + i * 4], Bb + (size_t)(jBase + sr) * HD + cb + i * 4);
    cp_commit();

    float acc[2][8][4];
#pragma unroll
    for (int i = 0; i < 2; ++i)
#pragma unroll
        for (int j = 0; j < 8; ++j)
#pragma unroll
            for (int e = 0; e < 4; ++e) acc[i][j][e] = 0.f;

    cp_wait0();
    __syncthreads();

#pragma unroll
    for (int ks = 0; ks < 8; ++ks) {
        const int k = ks * 8;
        float a[2][4], b[8][2];
#pragma unroll
        for (int mt = 0; mt < 2; ++mt) {
            int m = warpM + mt * 16 + gm;
            a[mt][0] = Asm[m][k + kq];
            a[mt][1] = Asm[m + 8][k + kq];
            a[mt][2] = Asm[m][k + kq + 4];
            a[mt][3] = Asm[m + 8][k + kq + 4];
        }
#pragma unroll
        for (int nt = 0; nt < 8; ++nt) {
            int n = warpN + nt * 8 + gm;
            b[nt][0] = Bsm[n][k + kq];
            b[nt][1] = Bsm[n][k + kq + 4];
        }
#pragma unroll
        for (int mt = 0; mt < 2; ++mt)
#pragma unroll
            for (int nt = 0; nt < 8; ++nt)
                mma_tf32(acc[mt][nt], a[mt], b[nt]);
    }

#pragma unroll
    for (int mt = 0; mt < 2; ++mt)
#pragma unroll
        for (int nt = 0; nt < 8; ++nt) {
            int r0 = iBase + warpM + mt * 16 + gm;
            int c0 = jBase + warpN + nt * 8 + kq * 2;
#pragma unroll
            for (int half = 0; half < 2; ++half)
                *(float2*)&Cb[(size_t)(r0 + half * 8) * NK2 + c0] =
                    make_float2(acc[mt][nt][half * 2], acc[mt][nt][half * 2 + 1]);
        }
}

// ============================================================================
// flash_tf32: fused scores(QK^T + rel-pos bias) -> online softmax -> PV.
// Whole-tile staging: X0 = K tile (Q at start), X1 = V tile. 73728 B dynamic.
// ============================================================================
__global__ __launch_bounds__(256, 1) void flash_tf32(
    const float* __restrict__ q, const float* __restrict__ k,
    const float* __restrict__ v,
    const float* __restrict__ c2p, const float* __restrict__ p2c,
    const int* __restrict__ tbl, float* __restrict__ ctx)
{
    extern __shared__ float smf[];
    float (*X0)[72] = (float(*)[72])smf;
    float (*X1)[72] = (float(*)[72])(smf + 128 * 72);

    const int t = threadIdx.x, l = t & 31, w = t >> 5;
    const int gm = l >> 2, kq = l & 3;
    const int warpM = w * 16;
    const int z = blockIdx.y;
    const int bz = z >> 4, h = z & 15;
    const int iBase = blockIdx.x * 128;

    const float* Qb = q + (size_t)z * NS * HD;
    const float* Kb = k + (size_t)z * NS * HD;
    const float* Vb = v + (size_t)z * NS * HD;
    const float* c2pr = c2p + (size_t)z * NS * NK2;
    const float* p2cr = p2c + (size_t)z * NS * NK2;

    const int sr = t >> 1, cb = (t & 1) * 32;
    const int i0 = iBase + warpM + gm;
    const int i1 = i0 + 8;

    // ---- load Q tile -> X0, extract fragments ----
#pragma unroll
    for (int i = 0; i < 8; ++i)
        cp16(&X0[sr][cb + i * 4], Qb + (size_t)(iBase + sr) * HD + cb + i * 4);
    cp_commit(); cp_wait0();
    __syncthreads();

    float aq[8][4];
    {
        int m = warpM + gm;
#pragma unroll
        for (int ks = 0; ks < 8; ++ks) {
            int kk = ks * 8;
            aq[ks][0] = X0[m][kk + kq];
            aq[ks][1] = X0[m + 8][kk + kq];
            aq[ks][2] = X0[m][kk + kq + 4];
            aq[ks][3] = X0[m + 8][kk + kq + 4];
        }
    }
    __syncthreads();

    // prefetch K(0) -> X0
#pragma unroll
    for (int i = 0; i < 8; ++i)
        cp16(&X0[sr][cb + i * 4], Kb + (size_t)sr * HD + cb + i * 4);
    cp_commit();   // pending: [K0]

    float m0 = -INFINITY, m1 = -INFINITY, l0 = 0.f, l1 = 0.f;
    float o[8][4];
#pragma unroll
    for (int i = 0; i < 8; ++i)
#pragma unroll
        for (int e = 0; e < 4; ++e) o[i][e] = 0.f;

    const float inv192 = 0.07216878364870322f;  // 1/sqrt(64*3)
    const float inv128 = 0.08838834764831845f;  // 1/sqrt(64*2)
    const int srcA = (l & ~3) | (kq >> 1);
    const int srcB = srcA + 2;
    const bool odd = (kq & 1);

    for (int jt = 0; jt < 8; ++jt) {
        const int jBase = jt * 128;

        // issue V(jt) -> X1 ; wait K(jt)
#pragma unroll
        for (int i = 0; i < 8; ++i)
            cp16(&X1[sr][cb + i * 4], Vb + (size_t)(jBase + sr) * HD + cb + i * 4);
        cp_commit();
        cp_wait1();
        __syncthreads();

        // ---- S = Q K^T ----
        float sc[16][4];
#pragma unroll
        for (int i = 0; i < 16; ++i)
#pragma unroll
            for (int e = 0; e < 4; ++e) sc[i][e] = 0.f;
#pragma unroll
        for (int ks = 0; ks < 8; ++ks) {
            const int kk = ks * 8;
#pragma unroll
            for (int nt = 0; nt < 16; ++nt) {
                int n = nt * 8 + gm;
                float b[2];
                b[0] = X0[n][kk + kq];
                b[1] = X0[n][kk + kq + 4];
                mma_tf32(sc[nt], aq[ks], b);
            }
        }
        __syncthreads();

        // prefetch K(jt+1) -> X0 (overlaps softmax)
        if (jt + 1 < 8) {
#pragma unroll
            for (int i = 0; i < 8; ++i)
                cp16(&X0[sr][cb + i * 4],
                     Kb + (size_t)((jt + 1) * 128 + sr) * HD + cb + i * 4);
            cp_commit();
        }

        // ---- bias epilogue ----
#pragma unroll
        for (int nt = 0; nt < 16; ++nt) {
#pragma unroll
            for (int e = 0; e < 4; ++e) {
                int i = (e < 2) ? i0 : i1;
                int j = jBase + nt * 8 + kq * 2 + (e & 1);
                int delta = i - j;
                int t1 = tbl[delta + (NS - 1)];
                int idx1 = min(max(t1 + SPAN, 0), 2 * SPAN - 1);
                int t2 = tbl[(NS - 1) - delta];
                int idx2 = min(max(SPAN - t2, 0), 2 * SPAN - 1);
                float bias = c2pr[(size_t)i * NK2 + idx1] + p2cr[(size_t)j * NK2 + idx2];
                sc[nt][e] = sc[nt][e] * inv192 + bias * inv128;
            }
        }

        // ---- online softmax ----
        float tm0 = -INFINITY, tm1 = -INFINITY;
#pragma unroll
        for (int nt = 0; nt < 16; ++nt) {
            tm0 = fmaxf(tm0, fmaxf(sc[nt][0], sc[nt][1]));
            tm1 = fmaxf(tm1, fmaxf(sc[nt][2], sc[nt][3]));
        }
        tm0 = fmaxf(tm0, __shfl_xor_sync(0xffffffffu, tm0, 1));
        tm0 = fmaxf(tm0, __shfl_xor_sync(0xffffffffu, tm0, 2));
        tm1 = fmaxf(tm1, __shfl_xor_sync(0xffffffffu, tm1, 1));
        tm1 = fmaxf(tm1, __shfl_xor_sync(0xffffffffu, tm1, 2));

        float mn0 = fmaxf(m0, tm0), mn1 = fmaxf(m1, tm1);
        float fac0 = expf(m0 - mn0), fac1 = expf(m1 - mn1);
        m0 = mn0; m1 = mn1;

        float s0 = 0.f, s1 = 0.f;
#pragma unroll
        for (int nt = 0; nt < 16; ++nt) {
            sc[nt][0] = f2tf(expf(sc[nt][0] - mn0));
            sc[nt][1] = f2tf(expf(sc[nt][1] - mn0));
            sc[nt][2] = f2tf(expf(sc[nt][2] - mn1));
            sc[nt][3] = f2tf(expf(sc[nt][3] - mn1));
            s0 += sc[nt][0] + sc[nt][1];
            s1 += sc[nt][2] + sc[nt][3];
        }
        s0 += __shfl_xor_sync(0xffffffffu, s0, 1);
        s0 += __shfl_xor_sync(0xffffffffu, s0, 2);
        s1 += __shfl_xor_sync(0xffffffffu, s1, 1);
        s1 += __shfl_xor_sync(0xffffffffu, s1, 2);
        l0 = l0 * fac0 + s0;
        l1 = l1 * fac1 + s1;

#pragma unroll
        for (int nt = 0; nt < 8; ++nt) {
            o[nt][0] *= fac0; o[nt][1] *= fac0;
            o[nt][2] *= fac1; o[nt][3] *= fac1;
        }

        // ---- wait V(jt), then PV ----
        if (jt + 1 < 8) cp_wait1(); else cp_wait0();
        __syncthreads();

#pragma unroll
        for (int ksg = 0; ksg < 16; ++ksg) {
            float e0 = __shfl_sync(0xffffffffu, sc[ksg][0], srcA);
            float e1 = __shfl_sync(0xffffffffu, sc[ksg][1], srcA);
            float e2 = __shfl_sync(0xffffffffu, sc[ksg][2], srcA);
            float e3 = __shfl_sync(0xffffffffu, sc[ksg][3], srcA);
            float f0 = __shfl_sync(0xffffffffu, sc[ksg][0], srcB);
            float f1 = __shfl_sync(0xffffffffu, sc[ksg][1], srcB);
            float f2 = __shfl_sync(0xffffffffu, sc[ksg][2], srcB);
            float f3 = __shfl_sync(0xffffffffu, sc[ksg][3], srcB);
            float pa[4];
            pa[0] = odd ? e1 : e0;
            pa[1] = odd ? e3 : e2;
            pa[2] = odd ? f1 : f0;
            pa[3] = odd ? f3 : f2;
#pragma unroll
            for (int nt = 0; nt < 8; ++nt) {
                int n = nt * 8 + gm;
                float b[2];
                b[0] = X1[ksg * 8 + kq][n];
                b[1] = X1[ksg * 8 + kq + 4][n];
                mma_tf32(o[nt], pa, b);
            }
        }
        __syncthreads();
    }

    // ---- normalize and store ctx ----
    float r0 = 1.0f / l0, r1 = 1.0f / l1;
#pragma unroll
    for (int nt = 0; nt < 8; ++nt) {
        int c0 = nt * 8 + kq * 2;
        *(float2*)&ctx[((size_t)bz * NS + i0) * ND + h * HD + c0] =
            make_float2(o[nt][0] * r0, o[nt][1] * r0);
        *(float2*)&ctx[((size_t)bz * NS + i1) * ND + h * HD + c0] =
            make_float2(o[nt][2] * r1, o[nt][3] * r1);
    }
}

// ---------------- launch ----------------
extern "C" void kernel_launch(void* const* d_in, const int* in_sizes, int n_in,
                              void* d_out, int out_size) {
    const float* hs    = (const float*)d_in[0];
    const float* Wq    = (const float*)d_in[1];
    const float* bq    = (const float*)d_in[2];
    const float* Wk    = (const float*)d_in[3];
    const float* bk    = (const float*)d_in[4];
    const float* Wv    = (const float*)d_in[5];
    const float* bv    = (const float*)d_in[6];
    const float* Wo    = (const float*)d_in[7];
    const float* bo    = (const float*)d_in[8];
    const float* rel   = (const float*)d_in[9];
    const float* ln_g  = (const float*)d_in[10];
    const float* ln_b  = (const float*)d_in[11];
    const float* Wpk   = (const float*)d_in[12];
    const float* bpk   = (const float*)d_in[13];
    const float* Wpq   = (const float*)d_in[14];
    const float* bpq   = (const float*)d_in[15];
    float* out = (float*)d_out;

    float *p_re, *p_q, *p_k, *p_v, *p_posk, *p_posq, *p_c2p, *p_p2c, *p_ctx;
    int* p_tbl;
    cudaGetSymbolAddress((void**)&p_re, g_re);
    cudaGetSymbolAddress((void**)&p_q, g_q);
    cudaGetSymbolAddress((void**)&p_k, g_k);
    cudaGetSymbolAddress((void**)&p_v, g_v);
    cudaGetSymbolAddress((void**)&p_posk, g_posk);
    cudaGetSymbolAddress((void**)&p_posq, g_posq);
    cudaGetSymbolAddress((void**)&p_c2p, g_c2p);
    cudaGetSymbolAddress((void**)&p_p2c, g_p2c);
    cudaGetSymbolAddress((void**)&p_ctx, g_ctx);
    cudaGetSymbolAddress((void**)&p_tbl, g_tbl);

    cudaFuncSetAttribute(mm_jobs_tf32,
                         cudaFuncAttributeMaxDynamicSharedMemorySize, 75776);
    cudaFuncSetAttribute(nt64_pair_tf32,
                         cudaFuncAttributeMaxDynamicSharedMemorySize, 73728);
    cudaFuncSetAttribute(flash_tf32,
                         cudaFuncAttributeMaxDynamicSharedMemorySize, 73728);

    build_tbl_kernel<<<9, 256>>>(p_tbl);
    ln_kernel<<<NK2, 256>>>(rel, ln_g, ln_b, p_re);

    // merged Q/K/V + pos-k/pos-q projections in one launch
    MMJobs jobs;
    jobs.j[0] = { hs,   Wq,  bq,  p_q,    NB * NS, NS  };
    jobs.j[1] = { hs,   Wk,  bk,  p_k,    NB * NS, NS  };
    jobs.j[2] = { hs,   Wv,  bv,  p_v,    NB * NS, NS  };
    jobs.j[3] = { p_re, Wpk, bpk, p_posk, NK2,     NK2 };
    jobs.j[4] = { p_re, Wpq, bpq, p_posq, NK2,     NK2 };
    mm_jobs_tf32<<<dim3(8, 32, 5), 256, 75776>>>(jobs);

    // c2p and p2c in one launch
    nt64_pair_tf32<<<dim3(4, 8, 128), 256, 73728>>>(p_q, p_posk, p_k, p_posq, p_c2p, p_p2c);

    // fused attention
    flash_tf32<<<dim3(8, 64), 256, 73728>>>(p_q, p_k, p_v, p_c2p, p_p2c, p_tbl, p_ctx);

    // out = ctx @ Wo + bo
    MMJobs jo;
    jo.j[0] = { p_ctx, Wo, bo, out, NB * NS, 0 };
    jo.j[1] = jo.j[0]; jo.j[2] = jo.j[0]; jo.j[3] = jo.j[0]; jo.j[4] = jo.j[0];
    mm_jobs_tf32<<<dim3(8, 32, 1), 256, 75776>>>(jo);
}

// round 10
// speedup vs baseline: 1.1051x; 1.1051x over previous
#include <cuda_runtime.h>
#include <cuda_bf16.h>
#include <math.h>

// Shapes (fixed by the problem)
#define NB 4
#define NH 16
#define NS 1024
#define ND 1024
#define HD 64
#define NK2 512   // 2 * BUCKETS
#define SPAN 256  // BUCKETS

// ---------------- scratch (device globals; no allocs allowed) ----------------
__device__ float g_re[NK2 * ND];
__device__ float g_q[(size_t)NB * NH * NS * HD];
__device__ float g_k[(size_t)NB * NH * NS * HD];
__device__ float g_v[(size_t)NB * NH * NS * HD];
__device__ float g_posk[NH * NK2 * HD];
__device__ float g_posq[NH * NK2 * HD];
__device__ __nv_bfloat16 g_c2p[(size_t)NB * NH * NS * NK2];  // pre-scaled by 1/sqrt(128)
__device__ __nv_bfloat16 g_p2c[(size_t)NB * NH * NS * NK2];  // pre-scaled by 1/sqrt(128)
__device__ float g_ctx[(size_t)NB * NS * ND];
__device__ int2  g_idx[2 * NS - 1];   // (idx1, idx2) per delta

// ---------------- helpers ----------------
__device__ __forceinline__ float f2tf(float x) {
    unsigned u;
    asm("cvt.rna.tf32.f32 %0, %1;" : "=r"(u) : "f"(x));
    return __uint_as_float(u);
}

__device__ __forceinline__ void mma_tf32(float* c, const float* a, const float* b) {
    asm volatile("mma.sync.aligned.m16n8k8.row.col.f32.tf32.tf32.f32 "
                 "{%0,%1,%2,%3}, {%4,%5,%6,%7}, {%8,%9}, {%0,%1,%2,%3};\n"
                 : "+f"(c[0]), "+f"(c[1]), "+f"(c[2]), "+f"(c[3])
                 : "r"(__float_as_uint(a[0])), "r"(__float_as_uint(a[1])),
                   "r"(__float_as_uint(a[2])), "r"(__float_as_uint(a[3])),
                   "r"(__float_as_uint(b[0])), "r"(__float_as_uint(b[1])));
}

__device__ __forceinline__ void cp16(float* dst, const float* src) {
    unsigned s = (unsigned)__cvta_generic_to_shared(dst);
    asm volatile("cp.async.cg.shared.global [%0], [%1], 16;" :: "r"(s), "l"(src));
}
__device__ __forceinline__ void cp_commit() { asm volatile("cp.async.commit_group;"); }
__device__ __forceinline__ void cp_wait0()  { asm volatile("cp.async.wait_group 0;"); }
__device__ __forceinline__ void cp_wait1()  { asm volatile("cp.async.wait_group 1;"); }

// ---------------- bucket + index table (matches jax f32 semantics) -----------
__device__ __forceinline__ int bucketf(int rel) {
    const float mid = 128.0f;
    float signf = (rel > 0) ? 1.0f : (rel < 0 ? -1.0f : 0.0f);
    float abs_pos = (rel < 128 && rel > -128) ? 127.0f : fabsf((float)rel);
    float bucket;
    if (abs_pos <= mid) {
        bucket = (float)rel;
    } else {
        const float LOGC = 1.3843393289f;  // log(511/128) as f32
        float log_pos = ceilf(logf(abs_pos / mid) / LOGC * 127.0f) + mid;
        bucket = log_pos * signf;
    }
    return (int)bucket;
}

__global__ void build_idx_kernel(int2* idx) {
    int i = blockIdx.x * blockDim.x + threadIdx.x;
    if (i >= 2 * NS - 1) return;
    int rel = i - (NS - 1);          // delta = i - j
    int b1 = bucketf(rel);
    int b2 = bucketf(-rel);
    int2 v;
    v.x = min(max(b1 + SPAN, 0), 2 * SPAN - 1);
    v.y = min(max(SPAN - b2, 0), 2 * SPAN - 1);
    idx[i] = v;
}

// ---------------- LayerNorm for rel_emb [512,1024] ----------------
__global__ void ln_kernel(const float* __restrict__ x, const float* __restrict__ g,
                          const float* __restrict__ b, float* __restrict__ y) {
    int row = blockIdx.x;
    const float* xr = x + (size_t)row * ND;
    __shared__ float red[256];
    int tid = threadIdx.x;

    float s = 0.f;
    for (int i = tid; i < ND; i += 256) s += xr[i];
    red[tid] = s; __syncthreads();
    for (int o = 128; o > 0; o >>= 1) { if (tid < o) red[tid] += red[tid + o]; __syncthreads(); }
    float mu = red[0] * (1.0f / ND);
    __syncthreads();

    float v = 0.f;
    for (int i = tid; i < ND; i += 256) { float d = xr[i] - mu; v += d * d; }
    red[tid] = v; __syncthreads();
    for (int o = 128; o > 0; o >>= 1) { if (tid < o) red[tid] += red[tid + o]; __syncthreads(); }
    float var = red[0] * (1.0f / ND);
    float inv = 1.0f / sqrtf(var + 1e-5f);

    for (int i = tid; i < ND; i += 256)
        y[(size_t)row * ND + i] = (xr[i] - mu) * inv * g[i] + b[i];
}

// ============================================================================
// mm_jobs_tf32: up to 5 independent GEMMs C = A[M,1024] @ W[1024,1024] + bias
// in one launch (blockIdx.z picks the job; oversized y-tiles early-exit).
// 128x128 tile, K-chunk 16, 2-stage cp.async, 2 CTAs/SM.  (round-7 version)
// ============================================================================
struct MMJob {
    const float* A; const float* W; const float* bias; float* C;
    int M; int splitR;   // splitR==0: row-major out; else head-split (+tf32 round)
};
struct MMJobs { MMJob j[5]; };

__global__ __launch_bounds__(256, 2) void mm_jobs_tf32(MMJobs jobs)
{
    __shared__ float As[2][128][20];
    __shared__ float Bs[2][16][136];

    const MMJob jb = jobs.j[blockIdx.z];
    if (blockIdx.y * 128 >= jb.M) return;
    const float* A = jb.A; const float* W = jb.W;
    const float* bias = jb.bias; float* C = jb.C;
    const int splitR = jb.splitR;

    const int t = threadIdx.x, l = t & 31, w = t >> 5;
    const int gm = l >> 2, kq = l & 3;
    const int warpM = (w >> 1) * 32, warpN = (w & 1) * 64;
    const int rowBase = blockIdx.y * 128, colBase = blockIdx.x * 128;

    float acc[2][8][4];
#pragma unroll
    for (int i = 0; i < 2; ++i)
#pragma unroll
        for (int j = 0; j < 8; ++j)
#pragma unroll
            for (int e = 0; e < 4; ++e) acc[i][j][e] = 0.f;

    const int ar = t >> 1, ac = (t & 1) * 8;
    const int bk = t >> 4, bc = (t & 15) * 8;

    cp16(&As[0][ar][ac],     A + (size_t)(rowBase + ar) * ND + ac);
    cp16(&As[0][ar][ac + 4], A + (size_t)(rowBase + ar) * ND + ac + 4);
    cp16(&Bs[0][bk][bc],     W + (size_t)bk * ND + colBase + bc);
    cp16(&Bs[0][bk][bc + 4], W + (size_t)bk * ND + colBase + bc + 4);
    cp_commit();

    for (int c = 0; c < ND / 16; ++c) {
        if (c + 1 < ND / 16) {
            int k0 = (c + 1) * 16, s = (c + 1) & 1;
            cp16(&As[s][ar][ac],     A + (size_t)(rowBase + ar) * ND + k0 + ac);
            cp16(&As[s][ar][ac + 4], A + (size_t)(rowBase + ar) * ND + k0 + ac + 4);
            cp16(&Bs[s][bk][bc],     W + (size_t)(k0 + bk) * ND + colBase + bc);
            cp16(&Bs[s][bk][bc + 4], W + (size_t)(k0 + bk) * ND + colBase + bc + 4);
            cp_commit();
            cp_wait1();
        } else {
            cp_wait0();
        }
        __syncthreads();

        const int s = c & 1;
#pragma unroll
        for (int ks = 0; ks < 2; ++ks) {
            const int k = ks * 8;
            float a[2][4], b[8][2];
#pragma unroll
            for (int mt = 0; mt < 2; ++mt) {
                int m = warpM + mt * 16 + gm;
                a[mt][0] = f2tf(As[s][m][k + kq]);
                a[mt][1] = f2tf(As[s][m + 8][k + kq]);
                a[mt][2] = f2tf(As[s][m][k + kq + 4]);
                a[mt][3] = f2tf(As[s][m + 8][k + kq + 4]);
            }
#pragma unroll
            for (int nt = 0; nt < 8; ++nt) {
                int n = warpN + nt * 8 + gm;
                b[nt][0] = f2tf(Bs[s][k + kq][n]);
                b[nt][1] = f2tf(Bs[s][k + kq + 4][n]);
            }
#pragma unroll
            for (int mt = 0; mt < 2; ++mt)
#pragma unroll
                for (int nt = 0; nt < 8; ++nt)
                    mma_tf32(acc[mt][nt], a[mt], b[nt]);
        }
        __syncthreads();
    }

#pragma unroll
    for (int mt = 0; mt < 2; ++mt) {
#pragma unroll
        for (int nt = 0; nt < 8; ++nt) {
            int r0 = rowBase + warpM + mt * 16 + gm;
            int c0 = colBase + warpN + nt * 8 + kq * 2;
#pragma unroll
            for (int half = 0; half < 2; ++half) {
                int r = r0 + half * 8;
                float v0 = acc[mt][nt][half * 2 + 0] + bias[c0];
                float v1 = acc[mt][nt][half * 2 + 1] + bias[c0 + 1];
                if (splitR == 0) {
                    *(float2*)&C[(size_t)r * ND + c0] = make_float2(v0, v1);
                } else {
                    v0 = f2tf(v0); v1 = f2tf(v1);
                    int h = c0 >> 6, d = c0 & 63;
                    int bb = r / splitR, rr = r - bb * splitR;
                    *(float2*)&C[(((size_t)bb * NH + h) * splitR + rr) * HD + d] =
                        make_float2(v0, v1);
                }
            }
        }
    }
}

// ============================================================================
// nt64_pair_tf32: c2p and p2c in one launch (round-7 structure).
// z<64:  C2P[z][i][kk] = q[z] . posk[z%16]      (bf16 out, pre-scaled)
// z>=64: P2C[z-64][i][kk] = k[z-64] . posq[..]  (bf16 out, pre-scaled)
// ============================================================================
__global__ __launch_bounds__(256, 2) void nt64_pair_tf32(
    const float* __restrict__ q, const float* __restrict__ posk,
    const float* __restrict__ kk, const float* __restrict__ posq,
    __nv_bfloat16* __restrict__ c2p, __nv_bfloat16* __restrict__ p2c)
{
    __shared__ float As[2][128][20];
    __shared__ float Bs[2][128][20];

    const int t = threadIdx.x, l = t & 31, w = t >> 5;
    const int gm = l >> 2, kq = l & 3;
    const int warpM = (w >> 1) * 32, warpN = (w & 1) * 64;
    const int zz = blockIdx.z;
    const int batch = zz & 63;
    const int iBase = blockIdx.y * 128, jBase = blockIdx.x * 128;

    const float* Ab = ((zz < 64) ? q : kk) + (size_t)batch * NS * HD;
    const float* Bb = ((zz < 64) ? posk : posq) + (size_t)(batch & 15) * NK2 * HD;
    __nv_bfloat16* Cb = ((zz < 64) ? c2p : p2c) + (size_t)batch * NS * NK2;

    float acc[2][8][4];
#pragma unroll
    for (int i = 0; i < 2; ++i)
#pragma unroll
        for (int j = 0; j < 8; ++j)
#pragma unroll
            for (int e = 0; e < 4; ++e) acc[i][j][e] = 0.f;

    const int sr = t >> 1, sc = (t & 1) * 8;

    cp16(&As[0][sr][sc],     Ab + (size_t)(iBase + sr) * HD + sc);
    cp16(&As[0][sr][sc + 4], Ab + (size_t)(iBase + sr) * HD + sc + 4);
    cp16(&Bs[0][sr][sc],     Bb + (size_t)(jBase + sr) * HD + sc);
    cp16(&Bs[0][sr][sc + 4], Bb + (size_t)(jBase + sr) * HD + sc + 4);
    cp_commit();

#pragma unroll
    for (int c = 0; c < 4; ++c) {
        if (c + 1 < 4) {
            int d0 = (c + 1) * 16, s = (c + 1) & 1;
            cp16(&As[s][sr][sc],     Ab + (size_t)(iBase + sr) * HD + d0 + sc);
            cp16(&As[s][sr][sc + 4], Ab + (size_t)(iBase + sr) * HD + d0 + sc + 4);
            cp16(&Bs[s][sr][sc],     Bb + (size_t)(jBase + sr) * HD + d0 + sc);
            cp16(&Bs[s][sr][sc + 4], Bb + (size_t)(jBase + sr) * HD + d0 + sc + 4);
            cp_commit();
            cp_wait1();
        } else {
            cp_wait0();
        }
        __syncthreads();

        const int s = c & 1;
#pragma unroll
        for (int ks = 0; ks < 2; ++ks) {
            const int k = ks * 8;
            float a[2][4], b[8][2];
#pragma unroll
            for (int mt = 0; mt < 2; ++mt) {
                int m = warpM + mt * 16 + gm;
                a[mt][0] = As[s][m][k + kq];
                a[mt][1] = As[s][m + 8][k + kq];
                a[mt][2] = As[s][m][k + kq + 4];
                a[mt][3] = As[s][m + 8][k + kq + 4];
            }
#pragma unroll
            for (int nt = 0; nt < 8; ++nt) {
                int n = warpN + nt * 8 + gm;
                b[nt][0] = Bs[s][n][k + kq];
                b[nt][1] = Bs[s][n][k + kq + 4];
            }
#pragma unroll
            for (int mt = 0; mt < 2; ++mt)
#pragma unroll
                for (int nt = 0; nt < 8; ++nt)
                    mma_tf32(acc[mt][nt], a[mt], b[nt]);
        }
        __syncthreads();
    }

    const float inv128 = 0.08838834764831845f;  // 1/sqrt(64*2) folded in here
#pragma unroll
    for (int mt = 0; mt < 2; ++mt)
#pragma unroll
        for (int nt = 0; nt < 8; ++nt) {
            int r0 = iBase + warpM + mt * 16 + gm;
            int c0 = jBase + warpN + nt * 8 + kq * 2;
#pragma unroll
            for (int half = 0; half < 2; ++half) {
                __nv_bfloat162 pk;
                pk.x = __float2bfloat16(acc[mt][nt][half * 2 + 0] * inv128);
                pk.y = __float2bfloat16(acc[mt][nt][half * 2 + 1] * inv128);
                *(__nv_bfloat162*)&Cb[(size_t)(r0 + half * 8) * NK2 + c0] = pk;
            }
        }
}

// ============================================================================
// flash_tf32: fused scores(QK^T + rel-pos bias) -> online softmax -> PV.
// Whole-tile staging: X0 = K tile (Q at start), X1 = V tile. 73728 B dynamic.
// Bias gathers read pre-scaled bf16 c2p/p2c via the combined int2 idx table.
// ============================================================================
__global__ __launch_bounds__(256, 1) void flash_tf32(
    const float* __restrict__ q, const float* __restrict__ k,
    const float* __restrict__ v,
    const __nv_bfloat16* __restrict__ c2p, const __nv_bfloat16* __restrict__ p2c,
    const int2* __restrict__ idxt, float* __restrict__ ctx)
{
    extern __shared__ float smf[];
    float (*X0)[72] = (float(*)[72])smf;
    float (*X1)[72] = (float(*)[72])(smf + 128 * 72);

    const int t = threadIdx.x, l = t & 31, w = t >> 5;
    const int gm = l >> 2, kq = l & 3;
    const int warpM = w * 16;
    const int z = blockIdx.y;
    const int bz = z >> 4, h = z & 15;
    const int iBase = blockIdx.x * 128;

    const float* Qb = q + (size_t)z * NS * HD;
    const float* Kb = k + (size_t)z * NS * HD;
    const float* Vb = v + (size_t)z * NS * HD;
    const __nv_bfloat16* c2pr = c2p + (size_t)z * NS * NK2;
    const __nv_bfloat16* p2cr = p2c + (size_t)z * NS * NK2;

    const int sr = t >> 1, cb = (t & 1) * 32;
    const int i0 = iBase + warpM + gm;
    const int i1 = i0 + 8;

    // ---- load Q tile -> X0, extract fragments ----
#pragma unroll
    for (int i = 0; i < 8; ++i)
        cp16(&X0[sr][cb + i * 4], Qb + (size_t)(iBase + sr) * HD + cb + i * 4);
    cp_commit(); cp_wait0();
    __syncthreads();

    float aq[8][4];
    {
        int m = warpM + gm;
#pragma unroll
        for (int ks = 0; ks < 8; ++ks) {
            int kk = ks * 8;
            aq[ks][0] = X0[m][kk + kq];
            aq[ks][1] = X0[m + 8][kk + kq];
            aq[ks][2] = X0[m][kk + kq + 4];
            aq[ks][3] = X0[m + 8][kk + kq + 4];
        }
    }
    __syncthreads();

    // prefetch K(0) -> X0
#pragma unroll
    for (int i = 0; i < 8; ++i)
        cp16(&X0[sr][cb + i * 4], Kb + (size_t)sr * HD + cb + i * 4);
    cp_commit();   // pending: [K0]

    float m0 = -INFINITY, m1 = -INFINITY, l0 = 0.f, l1 = 0.f;
    float o[8][4];
#pragma unroll
    for (int i = 0; i < 8; ++i)
#pragma unroll
        for (int e = 0; e < 4; ++e) o[i][e] = 0.f;

    const float inv192 = 0.07216878364870322f;  // 1/sqrt(64*3)
    const int srcA = (l & ~3) | (kq >> 1);
    const int srcB = srcA + 2;
    const bool odd = (kq & 1);

    for (int jt = 0; jt < 8; ++jt) {
        const int jBase = jt * 128;

        // issue V(jt) -> X1 ; wait K(jt)
#pragma unroll
        for (int i = 0; i < 8; ++i)
            cp16(&X1[sr][cb + i * 4], Vb + (size_t)(jBase + sr) * HD + cb + i * 4);
        cp_commit();
        cp_wait1();
        __syncthreads();

        // ---- S = Q K^T ----
        float sc[16][4];
#pragma unroll
        for (int i = 0; i < 16; ++i)
#pragma unroll
            for (int e = 0; e < 4; ++e) sc[i][e] = 0.f;
#pragma unroll
        for (int ks = 0; ks < 8; ++ks) {
            const int kk = ks * 8;
#pragma unroll
            for (int nt = 0; nt < 16; ++nt) {
                int n = nt * 8 + gm;
                float b[2];
                b[0] = X0[n][kk + kq];
                b[1] = X0[n][kk + kq + 4];
                mma_tf32(sc[nt], aq[ks], b);
            }
        }
        __syncthreads();

        // prefetch K(jt+1) -> X0 (overlaps softmax)
        if (jt + 1 < 8) {
#pragma unroll
            for (int i = 0; i < 8; ++i)
                cp16(&X0[sr][cb + i * 4],
                     Kb + (size_t)((jt + 1) * 128 + sr) * HD + cb + i * 4);
            cp_commit();
        }

        // ---- bias epilogue (bf16 gathers, combined idx table) ----
#pragma unroll
        for (int nt = 0; nt < 16; ++nt) {
#pragma unroll
            for (int e = 0; e < 4; ++e) {
                int i = (e < 2) ? i0 : i1;
                int j = jBase + nt * 8 + kq * 2 + (e & 1);
                int2 ip = idxt[i - j + (NS - 1)];
                float bias = __bfloat162float(c2pr[(size_t)i * NK2 + ip.x])
                           + __bfloat162float(p2cr[(size_t)j * NK2 + ip.y]);
                sc[nt][e] = sc[nt][e] * inv192 + bias;
            }
        }

        // ---- online softmax ----
        float tm0 = -INFINITY, tm1 = -INFINITY;
#pragma unroll
        for (int nt = 0; nt < 16; ++nt) {
            tm0 = fmaxf(tm0, fmaxf(sc[nt][0], sc[nt][1]));
            tm1 = fmaxf(tm1, fmaxf(sc[nt][2], sc[nt][3]));
        }
        tm0 = fmaxf(tm0, __shfl_xor_sync(0xffffffffu, tm0, 1));
        tm0 = fmaxf(tm0, __shfl_xor_sync(0xffffffffu, tm0, 2));
        tm1 = fmaxf(tm1, __shfl_xor_sync(0xffffffffu, tm1, 1));
        tm1 = fmaxf(tm1, __shfl_xor_sync(0xffffffffu, tm1, 2));

        float mn0 = fmaxf(m0, tm0), mn1 = fmaxf(m1, tm1);
        float fac0 = expf(m0 - mn0), fac1 = expf(m1 - mn1);
        m0 = mn0; m1 = mn1;

        float s0 = 0.f, s1 = 0.f;
#pragma unroll
        for (int nt = 0; nt < 16; ++nt) {
            sc[nt][0] = f2tf(expf(sc[nt][0] - mn0));
            sc[nt][1] = f2tf(expf(sc[nt][1] - mn0));
            sc[nt][2] = f2tf(expf(sc[nt][2] - mn1));
            sc[nt][3] = f2tf(expf(sc[nt][3] - mn1));
            s0 += sc[nt][0] + sc[nt][1];
            s1 += sc[nt][2] + sc[nt][3];
        }
        s0 += __shfl_xor_sync(0xffffffffu, s0, 1);
        s0 += __shfl_xor_sync(0xffffffffu, s0, 2);
        s1 += __shfl_xor_sync(0xffffffffu, s1, 1);
        s1 += __shfl_xor_sync(0xffffffffu, s1, 2);
        l0 = l0 * fac0 + s0;
        l1 = l1 * fac1 + s1;

#pragma unroll
        for (int nt = 0; nt < 8; ++nt) {
            o[nt][0] *= fac0; o[nt][1] *= fac0;
            o[nt][2] *= fac1; o[nt][3] *= fac1;
        }

        // ---- wait V(jt), then PV ----
        if (jt + 1 < 8) cp_wait1(); else cp_wait0();
        __syncthreads();

#pragma unroll
        for (int ksg = 0; ksg < 16; ++ksg) {
            float e0 = __shfl_sync(0xffffffffu, sc[ksg][0], srcA);
            float e1 = __shfl_sync(0xffffffffu, sc[ksg][1], srcA);
            float e2 = __shfl_sync(0xffffffffu, sc[ksg][2], srcA);
            float e3 = __shfl_sync(0xffffffffu, sc[ksg][3], srcA);
            float f0 = __shfl_sync(0xffffffffu, sc[ksg][0], srcB);
            float f1 = __shfl_sync(0xffffffffu, sc[ksg][1], srcB);
            float f2 = __shfl_sync(0xffffffffu, sc[ksg][2], srcB);
            float f3 = __shfl_sync(0xffffffffu, sc[ksg][3], srcB);
            float pa[4];
            pa[0] = odd ? e1 : e0;
            pa[1] = odd ? e3 : e2;
            pa[2] = odd ? f1 : f0;
            pa[3] = odd ? f3 : f2;
#pragma unroll
            for (int nt = 0; nt < 8; ++nt) {
                int n = nt * 8 + gm;
                float b[2];
                b[0] = X1[ksg * 8 + kq][n];
                b[1] = X1[ksg * 8 + kq + 4][n];
                mma_tf32(o[nt], pa, b);
            }
        }
        __syncthreads();
    }

    // ---- normalize and store ctx ----
    float r0 = 1.0f / l0, r1 = 1.0f / l1;
#pragma unroll
    for (int nt = 0; nt < 8; ++nt) {
        int c0 = nt * 8 + kq * 2;
        *(float2*)&ctx[((size_t)bz * NS + i0) * ND + h * HD + c0] =
            make_float2(o[nt][0] * r0, o[nt][1] * r0);
        *(float2*)&ctx[((size_t)bz * NS + i1) * ND + h * HD + c0] =
            make_float2(o[nt][2] * r1, o[nt][3] * r1);
    }
}

// ---------------- launch ----------------
extern "C" void kernel_launch(void* const* d_in, const int* in_sizes, int n_in,
                              void* d_out, int out_size) {
    const float* hs    = (const float*)d_in[0];
    const float* Wq    = (const float*)d_in[1];
    const float* bq    = (const float*)d_in[2];
    const float* Wk    = (const float*)d_in[3];
    const float* bk    = (const float*)d_in[4];
    const float* Wv    = (const float*)d_in[5];
    const float* bv    = (const float*)d_in[6];
    const float* Wo    = (const float*)d_in[7];
    const float* bo    = (const float*)d_in[8];
    const float* rel   = (const float*)d_in[9];
    const float* ln_g  = (const float*)d_in[10];
    const float* ln_b  = (const float*)d_in[11];
    const float* Wpk   = (const float*)d_in[12];
    const float* bpk   = (const float*)d_in[13];
    const float* Wpq   = (const float*)d_in[14];
    const float* bpq   = (const float*)d_in[15];
    float* out = (float*)d_out;

    float *p_re, *p_q, *p_k, *p_v, *p_posk, *p_posq, *p_ctx;
    __nv_bfloat16 *p_c2p, *p_p2c;
    int2* p_idx;
    cudaGetSymbolAddress((void**)&p_re, g_re);
    cudaGetSymbolAddress((void**)&p_q, g_q);
    cudaGetSymbolAddress((void**)&p_k, g_k);
    cudaGetSymbolAddress((void**)&p_v, g_v);
    cudaGetSymbolAddress((void**)&p_posk, g_posk);
    cudaGetSymbolAddress((void**)&p_posq, g_posq);
    cudaGetSymbolAddress((void**)&p_c2p, g_c2p);
    cudaGetSymbolAddress((void**)&p_p2c, g_p2c);
    cudaGetSymbolAddress((void**)&p_ctx, g_ctx);
    cudaGetSymbolAddress((void**)&p_idx, g_idx);

    static bool attr_done = false;
    if (!attr_done) {
        cudaFuncSetAttribute(flash_tf32,
                             cudaFuncAttributeMaxDynamicSharedMemorySize, 73728);
        attr_done = true;
    }

    build_idx_kernel<<<9, 256>>>(p_idx);
    ln_kernel<<<NK2, 256>>>(rel, ln_g, ln_b, p_re);

    // merged Q/K/V + pos-k/pos-q projections in one launch
    MMJobs jobs;
    jobs.j[0] = { hs,   Wq,  bq,  p_q,    NB * NS, NS  };
    jobs.j[1] = { hs,   Wk,  bk,  p_k,    NB * NS, NS  };
    jobs.j[2] = { hs,   Wv,  bv,  p_v,    NB * NS, NS  };
    jobs.j[3] = { p_re, Wpk, bpk, p_posk, NK2,     NK2 };
    jobs.j[4] = { p_re, Wpq, bpq, p_posq, NK2,     NK2 };
    mm_jobs_tf32<<<dim3(8, 32, 5), 256>>>(jobs);

    // c2p and p2c in one launch (bf16, pre-scaled)
    nt64_pair_tf32<<<dim3(4, 8, 128), 256>>>(p_q, p_posk, p_k, p_posq, p_c2p, p_p2c);

    // fused attention
    flash_tf32<<<dim3(8, 64), 256, 73728>>>(p_q, p_k, p_v, p_c2p, p_p2c, p_idx, p_ctx);

    // out = ctx @ Wo + bo
    MMJobs jo;
    jo.j[0] = { p_ctx, Wo, bo, out, NB * NS, 0 };
    jo.j[1] = jo.j[0]; jo.j[2] = jo.j[0]; jo.j[3] = jo.j[0]; jo.j[4] = jo.j[0];
    mm_jobs_tf32<<<dim3(8, 32, 1), 256>>>(jo);
}